// round 7
// baseline (speedup 1.0000x reference)
#include <cuda_runtime.h>
#include <cuda_bf16.h>
#include <math.h>
#include <stdint.h>

// Problem constants
#define BB   8
#define CQ   1024
#define CR   512
#define HID  256
#define NP   2304          // H*W = 48*48

#define KC   16            // k per smem stage
#define PS   20            // smem words per row: 8 hi-pair + 8 lo-pair + 4 pad

// ---------------------------------------------------------------------------
// Device-global scratch. "Planes" are bf16 hi/lo pairs packed in u32.
// ---------------------------------------------------------------------------
__device__ uint32_t g_qfT_hi[(size_t)BB * NP * CQ / 2];   // [b][i][c]
__device__ uint32_t g_qfT_lo[(size_t)BB * NP * CQ / 2];
__device__ uint32_t g_rfT_hi[(size_t)BB * NP * CR / 2];   // [b][p][c]
__device__ uint32_t g_rfT_lo[(size_t)BB * NP * CR / 2];
__device__ uint32_t g_rfS_hi[(size_t)BB * CR * NP / 2];   // [b][c][p]
__device__ uint32_t g_rfS_lo[(size_t)BB * CR * NP / 2];
__device__ uint32_t g_Wq_hi[(size_t)HID * CQ / 2];
__device__ uint32_t g_Wq_lo[(size_t)HID * CQ / 2];
__device__ uint32_t g_Wk_hi[(size_t)HID * CR / 2];
__device__ uint32_t g_Wk_lo[(size_t)HID * CR / 2];
__device__ uint32_t g_Q_hi[(size_t)BB * NP * HID / 2];    // [b][i][o]
__device__ uint32_t g_Q_lo[(size_t)BB * NP * HID / 2];
__device__ uint32_t g_K_hi[(size_t)BB * NP * HID / 2];    // [b][p][o]
__device__ uint32_t g_K_lo[(size_t)BB * NP * HID / 2];
__device__ float    g_attn[(size_t)BB * NP * NP];         // [b][i][p] fp32 logits
__device__ uint32_t g_at_hi[(size_t)BB * NP * NP / 2];    // [b][i][p] probs
__device__ uint32_t g_at_lo[(size_t)BB * NP * NP / 2];

// ---------------------------------------------------------------------------
// helpers
// ---------------------------------------------------------------------------
__device__ __forceinline__ void split_bf16(float x, unsigned short &h, unsigned short &l) {
    __nv_bfloat16 hb = __float2bfloat16_rn(x);
    h = __bfloat16_as_ushort(hb);
    float r = x - __bfloat162float(hb);
    l = __bfloat16_as_ushort(__float2bfloat16_rn(r));
}
__device__ __forceinline__ void split_pair_words(float x0, float x1,
                                                 uint32_t &hw, uint32_t &lw) {
    unsigned short h0, l0, h1, l1;
    split_bf16(x0, h0, l0);
    split_bf16(x1, h1, l1);
    hw = (uint32_t)h0 | ((uint32_t)h1 << 16);
    lw = (uint32_t)l0 | ((uint32_t)l1 << 16);
}

__device__ __forceinline__ void mma_bf16(float c[4], const uint32_t a[4],
                                         const uint32_t b0, const uint32_t b1) {
    asm volatile(
        "mma.sync.aligned.m16n8k16.row.col.f32.bf16.bf16.f32 "
        "{%0,%1,%2,%3}, {%4,%5,%6,%7}, {%8,%9}, {%0,%1,%2,%3};\n"
        : "+f"(c[0]), "+f"(c[1]), "+f"(c[2]), "+f"(c[3])
        : "r"(a[0]), "r"(a[1]), "r"(a[2]), "r"(a[3]),
          "r"(b0), "r"(b1));
}

__device__ __forceinline__ void ldsm4(uint32_t r[4], uint32_t addr) {
    asm volatile("ldmatrix.sync.aligned.m8n8.x4.shared.b16 {%0,%1,%2,%3}, [%4];"
                 : "=r"(r[0]), "=r"(r[1]), "=r"(r[2]), "=r"(r[3]) : "r"(addr));
}
__device__ __forceinline__ void cpasync16(uint32_t saddr, const void* g) {
    asm volatile("cp.async.cg.shared.global [%0], [%1], 16;" :: "r"(saddr), "l"(g));
}
#define CP_COMMIT() asm volatile("cp.async.commit_group;" ::: "memory")
#define CP_WAIT0()  asm volatile("cp.async.wait_group 0;" ::: "memory")

// ---------------------------------------------------------------------------
// Elementwise split: fp32 -> hi/lo bf16 planes (pairs packed in u32).
// ---------------------------------------------------------------------------
__global__ void __launch_bounds__(256) split_pairs(
    const float* __restrict__ src,
    uint32_t* __restrict__ dhi, uint32_t* __restrict__ dlo, size_t npairs)
{
    size_t i = (size_t)blockIdx.x * 256 + threadIdx.x;
    if (i >= npairs) return;
    float x0 = src[2 * i], x1 = src[2 * i + 1];
    uint32_t hw, lw;
    split_pair_words(x0, x1, hw, lw);
    dhi[i] = hw;
    dlo[i] = lw;
}

// ---------------------------------------------------------------------------
// Tiled transpose + split: src fp32 [R][C] -> dst hi/lo bf16 [C][R].
// ---------------------------------------------------------------------------
__global__ void __launch_bounds__(256) transpose_split(
    const float* __restrict__ src,
    uint32_t* __restrict__ dhi, uint32_t* __restrict__ dlo,
    int R, int C)
{
    __shared__ float s[64][33];
    const int b = blockIdx.z;
    src += (size_t)b * R * C;
    const size_t dbatch = (size_t)C * (R >> 1);
    dhi += (size_t)b * dbatch;
    dlo += (size_t)b * dbatch;

    const int c0 = blockIdx.x * 32;
    const int r0 = blockIdx.y * 64;
    const int tx = threadIdx.x, ty = threadIdx.y;

    #pragma unroll
    for (int j = 0; j < 8; j++) {
        const int r = ty + 8 * j;
        s[r][tx] = src[(size_t)(r0 + r) * C + c0 + tx];
    }
    __syncthreads();

    #pragma unroll
    for (int j = 0; j < 4; j++) {
        const int cl = ty + 8 * j;
        const float x0 = s[2 * tx][cl];
        const float x1 = s[2 * tx + 1][cl];
        uint32_t hw, lw;
        split_pair_words(x0, x1, hw, lw);
        const size_t o = (size_t)(c0 + cl) * (R >> 1) + (r0 >> 1) + tx;
        dhi[o] = hw;
        dlo[o] = lw;
    }
}

// ---------------------------------------------------------------------------
// Split-bf16 tensor-core GEMM, cp.async double buffer + ldmatrix fragments.
//   C[m][n] = sum_k A[m][k] * B[n][k]  (both operands R-layout hi/lo planes)
// 128x128 CTA tile, 256 threads, 8 warps = 2(m) x 4(n), warp tile 64x32,
// m16n8k16 atoms, 3 MMAs per atom (ah*bh + ah*bl + al*bh), fp32 accumulate.
// Term-outer MMA ordering: the 48 MMAs per chunk are issued as three blocks
// of 16 MMAs with all-distinct accumulators (no back-to-back RAW on acc).
// ---------------------------------------------------------------------------
template<bool BIAS, bool OSPLIT>
__global__ void __launch_bounds__(256, 2) bgemm(
    const uint32_t* __restrict__ Ahi32, const uint32_t* __restrict__ Alo32,
    int lda, size_t sA,
    const uint32_t* __restrict__ Bhi32, const uint32_t* __restrict__ Blo32,
    int ldb, size_t sB,
    const float* __restrict__ bias,
    float* __restrict__ C, uint32_t* __restrict__ Chi, uint32_t* __restrict__ Clo,
    int ldc, size_t sC, int Ktot)
{
    __shared__ uint32_t As[2][128 * PS];
    __shared__ uint32_t Bs[2][128 * PS];

    const int bz = blockIdx.z;
    const __nv_bfloat16* Ahi = (const __nv_bfloat16*)Ahi32 + sA * bz;
    const __nv_bfloat16* Alo = (const __nv_bfloat16*)Alo32 + sA * bz;
    const __nv_bfloat16* Bhi = (const __nv_bfloat16*)Bhi32 + sB * bz;
    const __nv_bfloat16* Blo = (const __nv_bfloat16*)Blo32 + sB * bz;

    const int tid = threadIdx.x;
    const int m0  = blockIdx.x * 128;
    const int n0  = blockIdx.y * 128;

    // cp.async loader: thread -> (row, plane); copies 2x16B per operand/stage
    const int lrow = tid >> 1;
    const int lpl  = tid & 1;
    const __nv_bfloat16* Asrc = (lpl ? Alo : Ahi) + (size_t)(m0 + lrow) * lda;
    const __nv_bfloat16* Bsrc = (lpl ? Blo : Bhi) + (size_t)(n0 + lrow) * ldb;
    const uint32_t sdst = (uint32_t)(lrow * PS + lpl * 8) * 4;   // bytes in stage

    const uint32_t aS = (uint32_t)__cvta_generic_to_shared(&As[0][0]);
    const uint32_t bS = (uint32_t)__cvta_generic_to_shared(&Bs[0][0]);
    const uint32_t stageB = 128 * PS * 4;

    // warp/lane decomposition
    const int wid = tid >> 5, lane = tid & 31;
    const int wm = (wid & 1) * 64;
    const int wn = (wid >> 1) * 32;
    const int qr = lane >> 2, qc = lane & 3;

    // ldmatrix per-lane addresses (byte offsets within a stage)
    uint32_t aoff[4], boff[4];
    {
        const int arl = (lane & 7) + (lane & 8);
        const int awd = (lane & 16) ? 4 : 0;
        #pragma unroll
        for (int mt = 0; mt < 4; mt++)
            aoff[mt] = (uint32_t)(((wm + mt * 16 + arl) * PS + awd) * 4);
        const int brl = lane & 7;
        const int bwd = ((lane >> 3) & 3) * 4;
        #pragma unroll
        for (int nt = 0; nt < 4; nt++)
            boff[nt] = (uint32_t)(((wn + nt * 8 + brl) * PS + bwd) * 4);
    }

    float acc[4][4][4];
    #pragma unroll
    for (int mt = 0; mt < 4; mt++)
        #pragma unroll
        for (int nt = 0; nt < 4; nt++)
            #pragma unroll
            for (int r = 0; r < 4; r++) acc[mt][nt][r] = 0.f;

    // ---- prologue: stage 0 ----
    cpasync16(aS + sdst,      Asrc);
    cpasync16(aS + sdst + 16, Asrc + 8);
    cpasync16(bS + sdst,      Bsrc);
    cpasync16(bS + sdst + 16, Bsrc + 8);
    CP_COMMIT();
    CP_WAIT0();
    __syncthreads();

    const int nk = Ktot / KC;
    int buf = 0;
    for (int kb = 0; kb < nk; kb++) {
        const bool has_next = (kb + 1) < nk;
        if (has_next) {
            const int k0 = (kb + 1) * KC;
            const uint32_t ad = aS + (buf ^ 1) * stageB + sdst;
            const uint32_t bd = bS + (buf ^ 1) * stageB + sdst;
            cpasync16(ad,      Asrc + k0);
            cpasync16(ad + 16, Asrc + k0 + 8);
            cpasync16(bd,      Bsrc + k0);
            cpasync16(bd + 16, Bsrc + k0 + 8);
            CP_COMMIT();
        }

        const uint32_t ab = aS + buf * stageB;
        const uint32_t bb = bS + buf * stageB;

        uint32_t ah[4][4], al[4][4], bv[4][4];    // bv: {b0h, b1h, b0l, b1l}
        #pragma unroll
        for (int mt = 0; mt < 4; mt++) {
            ldsm4(ah[mt], ab + aoff[mt]);          // hi plane (words 0..7)
            ldsm4(al[mt], ab + aoff[mt] + 32);     // lo plane (words 8..15)
        }
        #pragma unroll
        for (int nt = 0; nt < 4; nt++)
            ldsm4(bv[nt], bb + boff[nt]);

        // term 1: ah * bl  (16 independent accumulators)
        #pragma unroll
        for (int nt = 0; nt < 4; nt++)
            #pragma unroll
            for (int mt = 0; mt < 4; mt++)
                mma_bf16(acc[mt][nt], ah[mt], bv[nt][2], bv[nt][3]);
        // term 2: al * bh
        #pragma unroll
        for (int nt = 0; nt < 4; nt++)
            #pragma unroll
            for (int mt = 0; mt < 4; mt++)
                mma_bf16(acc[mt][nt], al[mt], bv[nt][0], bv[nt][1]);
        // term 3: ah * bh
        #pragma unroll
        for (int nt = 0; nt < 4; nt++)
            #pragma unroll
            for (int mt = 0; mt < 4; mt++)
                mma_bf16(acc[mt][nt], ah[mt], bv[nt][0], bv[nt][1]);

        if (has_next) {
            CP_WAIT0();
            __syncthreads();
            buf ^= 1;
        }
    }

    // ---- epilogue ----
    #pragma unroll
    for (int mt = 0; mt < 4; mt++) {
        #pragma unroll
        for (int nt = 0; nt < 4; nt++) {
            const int row = m0 + wm + mt * 16 + qr;
            const int col = n0 + wn + nt * 8 + 2 * qc;
            float v0 = acc[mt][nt][0], v1 = acc[mt][nt][1];
            float v2 = acc[mt][nt][2], v3 = acc[mt][nt][3];
            if (BIAS) {
                const float b0 = bias[col], b1 = bias[col + 1];
                v0 += b0; v1 += b1; v2 += b0; v3 += b1;
            }
            if (OSPLIT) {
                uint32_t* chb = Chi + (size_t)bz * (sC >> 1);
                uint32_t* clb = Clo + (size_t)bz * (sC >> 1);
                uint32_t hw, lw;
                split_pair_words(v0, v1, hw, lw);
                size_t o = (size_t)row * (ldc >> 1) + (col >> 1);
                chb[o] = hw; clb[o] = lw;
                split_pair_words(v2, v3, hw, lw);
                o = (size_t)(row + 8) * (ldc >> 1) + (col >> 1);
                chb[o] = hw; clb[o] = lw;
            } else {
                float* cb = C + sC * bz;
                *(float2*)&cb[(size_t)row * ldc + col]       = make_float2(v0, v1);
                *(float2*)&cb[(size_t)(row + 8) * ldc + col] = make_float2(v2, v3);
            }
        }
    }
}

// ---------------------------------------------------------------------------
// Fused row softmax + bf16 split: S[b][i][p] fp32 -> prob planes [b][i][p].
// One CTA per row (2304 elements cached in smem), 256 threads.
// ---------------------------------------------------------------------------
__global__ void __launch_bounds__(256) softmax_split(
    const float* __restrict__ S,
    uint32_t* __restrict__ ph_out, uint32_t* __restrict__ pl_out)
{
    __shared__ float row[NP];
    __shared__ float red[9];
    const int b = blockIdx.y, i = blockIdx.x, t = threadIdx.x;
    const int wid = t >> 5, lane = t & 31;
    const float* src = S + ((size_t)b * NP + i) * NP;

    float lm = -3.402823466e38f;
    #pragma unroll
    for (int j = 0; j < 9; j++) {
        const int idx = j * 256 + t;
        const float x = src[idx];
        row[idx] = x;
        lm = fmaxf(lm, x);
    }
    #pragma unroll
    for (int o = 16; o; o >>= 1) lm = fmaxf(lm, __shfl_xor_sync(0xffffffffu, lm, o));
    if (lane == 0) red[wid] = lm;
    __syncthreads();
    if (t == 0) {
        float M = red[0];
        #pragma unroll
        for (int k = 1; k < 8; k++) M = fmaxf(M, red[k]);
        red[8] = M;
    }
    __syncthreads();
    const float M = red[8];

    float ls = 0.f;
    #pragma unroll
    for (int j = 0; j < 9; j++) {
        const int idx = j * 256 + t;
        const float e = __expf(row[idx] - M);
        row[idx] = e;
        ls += e;
    }
    #pragma unroll
    for (int o = 16; o; o >>= 1) ls += __shfl_xor_sync(0xffffffffu, ls, o);
    if (lane == 0) red[wid] = ls;
    __syncthreads();
    if (t == 0) {
        float s2 = 0.f;
        #pragma unroll
        for (int k = 0; k < 8; k++) s2 += red[k];
        red[8] = 1.0f / s2;
    }
    __syncthreads();
    const float inv = red[8];

    uint32_t* oh = ph_out + ((size_t)b * NP + i) * (NP / 2);
    uint32_t* ol = pl_out + ((size_t)b * NP + i) * (NP / 2);
    #pragma unroll
    for (int j = 0; j < 5; j++) {
        const int q = j * 256 + t;
        if (q < NP / 2) {
            const float2 xv = *(const float2*)&row[2 * q];
            uint32_t hw, lw;
            split_pair_words(xv.x * inv, xv.y * inv, hw, lw);
            oh[q] = hw;
            ol[q] = lw;
        }
    }
}

// ---------------------------------------------------------------------------
extern "C" void kernel_launch(void* const* d_in, const int* in_sizes, int n_in,
                              void* d_out, int out_size)
{
    const float* qf = (const float*)d_in[0];   // [B, CQ, 48, 48]
    const float* rf = (const float*)d_in[1];   // [B, CR, 48, 48]
    const float* Wq = (const float*)d_in[2];   // [HID, CQ]
    const float* bq = (const float*)d_in[3];   // [HID]
    const float* Wk = (const float*)d_in[4];   // [HID, CR]
    const float* bk = (const float*)d_in[5];   // [HID]
    float* out = (float*)d_out;                // [B, CR, 48, 48]

    uint32_t *qfTh, *qfTl, *rfTh, *rfTl, *rfSh, *rfSl;
    uint32_t *Wqh, *Wql, *Wkh, *Wkl, *Qh, *Ql, *Kh, *Kl, *ath, *atl;
    float *Ap;
    cudaGetSymbolAddress((void**)&qfTh, g_qfT_hi);
    cudaGetSymbolAddress((void**)&qfTl, g_qfT_lo);
    cudaGetSymbolAddress((void**)&rfTh, g_rfT_hi);
    cudaGetSymbolAddress((void**)&rfTl, g_rfT_lo);
    cudaGetSymbolAddress((void**)&rfSh, g_rfS_hi);
    cudaGetSymbolAddress((void**)&rfSl, g_rfS_lo);
    cudaGetSymbolAddress((void**)&Wqh, g_Wq_hi);
    cudaGetSymbolAddress((void**)&Wql, g_Wq_lo);
    cudaGetSymbolAddress((void**)&Wkh, g_Wk_hi);
    cudaGetSymbolAddress((void**)&Wkl, g_Wk_lo);
    cudaGetSymbolAddress((void**)&Qh, g_Q_hi);
    cudaGetSymbolAddress((void**)&Ql, g_Q_lo);
    cudaGetSymbolAddress((void**)&Kh, g_K_hi);
    cudaGetSymbolAddress((void**)&Kl, g_K_lo);
    cudaGetSymbolAddress((void**)&ath, g_at_hi);
    cudaGetSymbolAddress((void**)&atl, g_at_lo);
    cudaGetSymbolAddress((void**)&Ap, g_attn);

    // ---- prepass: splits + transposes ----
    {
        size_t np;
        np = (size_t)HID * CQ / 2;
        split_pairs<<<(unsigned)((np + 255) / 256), 256>>>(Wq, Wqh, Wql, np);
        np = (size_t)HID * CR / 2;
        split_pairs<<<(unsigned)((np + 255) / 256), 256>>>(Wk, Wkh, Wkl, np);
        np = (size_t)BB * CR * NP / 2;
        split_pairs<<<(unsigned)((np + 255) / 256), 256>>>(rf, rfSh, rfSl, np);
    }
    transpose_split<<<dim3(NP / 32, CQ / 64, BB), dim3(32, 8)>>>(qf, qfTh, qfTl, CQ, NP);
    transpose_split<<<dim3(NP / 32, CR / 64, BB), dim3(32, 8)>>>(rf, rfTh, rfTl, CR, NP);

    // ---- GEMM1: Q[i][o] = qfT[i][c] * Wq[o][c] + bq -> hi/lo planes ----
    bgemm<true, true><<<dim3(NP / 128, HID / 128, BB), 256>>>(
        qfTh, qfTl, CQ, (size_t)NP * CQ,
        Wqh, Wql, CQ, 0,
        bq,
        nullptr, Qh, Ql, HID, (size_t)NP * HID,
        CQ);

    // ---- GEMM2: K[p][o] = rfT[p][c] * Wk[o][c] + bk -> hi/lo planes ----
    bgemm<true, true><<<dim3(NP / 128, HID / 128, BB), 256>>>(
        rfTh, rfTl, CR, (size_t)NP * CR,
        Wkh, Wkl, CR, 0,
        bk,
        nullptr, Kh, Kl, HID, (size_t)NP * HID,
        CR);

    // ---- GEMM3: S[i][p] = Q[i][k] * K[p][k]  (fp32 out) ----
    bgemm<false, false><<<dim3(NP / 128, NP / 128, BB), 256>>>(
        Qh, Ql, HID, (size_t)NP * HID,
        Kh, Kl, HID, (size_t)NP * HID,
        nullptr,
        Ap, nullptr, nullptr, NP, (size_t)NP * NP,
        HID);

    // ---- fused softmax over p + bf16 split to prob planes [i][p] ----
    softmax_split<<<dim3(NP, BB), 256>>>(Ap, ath, atl);

    // ---- GEMM4: out[c][i] = rfS[c][p] * attn[i][p]  (fp32 out) ----
    bgemm<false, false><<<dim3(CR / 128, NP / 128, BB), 256>>>(
        rfSh, rfSl, NP, (size_t)CR * NP,
        ath, atl, NP, (size_t)NP * NP,
        nullptr,
        out, nullptr, nullptr, NP, (size_t)CR * NP,
        NP);
}

// round 8
// speedup vs baseline: 1.5137x; 1.5137x over previous
#include <cuda_runtime.h>
#include <cuda_bf16.h>
#include <math.h>
#include <stdint.h>

// Problem constants
#define BB   8
#define CQ   1024
#define CR   512
#define HID  256
#define NP   2304          // H*W = 48*48

#define KC   16            // k per smem stage
#define PS   20            // smem words per row: 8 hi-pair + 8 lo-pair + 4 pad

// ---------------------------------------------------------------------------
// Device-global scratch. "Planes" are bf16 hi/lo pairs packed in u32.
// ---------------------------------------------------------------------------
__device__ uint32_t g_qfT_hi[(size_t)BB * NP * CQ / 2];   // [b][i][c]
__device__ uint32_t g_qfT_lo[(size_t)BB * NP * CQ / 2];
__device__ uint32_t g_rfT_hi[(size_t)BB * NP * CR / 2];   // [b][p][c]
__device__ uint32_t g_rfT_lo[(size_t)BB * NP * CR / 2];
__device__ uint32_t g_rfS_hi[(size_t)BB * CR * NP / 2];   // [b][c][p]
__device__ uint32_t g_rfS_lo[(size_t)BB * CR * NP / 2];
__device__ uint32_t g_Wq_hi[(size_t)HID * CQ / 2];
__device__ uint32_t g_Wq_lo[(size_t)HID * CQ / 2];
__device__ uint32_t g_Wk_hi[(size_t)HID * CR / 2];
__device__ uint32_t g_Wk_lo[(size_t)HID * CR / 2];
__device__ uint32_t g_Q_hi[(size_t)BB * NP * HID / 2];    // [b][i][o]
__device__ uint32_t g_Q_lo[(size_t)BB * NP * HID / 2];
__device__ uint32_t g_K_hi[(size_t)BB * NP * HID / 2];    // [b][p][o]
__device__ uint32_t g_K_lo[(size_t)BB * NP * HID / 2];
__device__ float    g_attn[(size_t)BB * NP * NP];         // [b][i][p] fp32 logits
__device__ uint32_t g_at_hi[(size_t)BB * NP * NP / 2];    // [b][i][p] probs
__device__ uint32_t g_at_lo[(size_t)BB * NP * NP / 2];

// ---------------------------------------------------------------------------
// helpers
// ---------------------------------------------------------------------------
__device__ __forceinline__ void split_bf16(float x, unsigned short &h, unsigned short &l) {
    __nv_bfloat16 hb = __float2bfloat16_rn(x);
    h = __bfloat16_as_ushort(hb);
    float r = x - __bfloat162float(hb);
    l = __bfloat16_as_ushort(__float2bfloat16_rn(r));
}
__device__ __forceinline__ void split_pair_words(float x0, float x1,
                                                 uint32_t &hw, uint32_t &lw) {
    unsigned short h0, l0, h1, l1;
    split_bf16(x0, h0, l0);
    split_bf16(x1, h1, l1);
    hw = (uint32_t)h0 | ((uint32_t)h1 << 16);
    lw = (uint32_t)l0 | ((uint32_t)l1 << 16);
}

__device__ __forceinline__ void mma_bf16(float c[4], const uint32_t a[4],
                                         const uint32_t b0, const uint32_t b1) {
    asm volatile(
        "mma.sync.aligned.m16n8k16.row.col.f32.bf16.bf16.f32 "
        "{%0,%1,%2,%3}, {%4,%5,%6,%7}, {%8,%9}, {%0,%1,%2,%3};\n"
        : "+f"(c[0]), "+f"(c[1]), "+f"(c[2]), "+f"(c[3])
        : "r"(a[0]), "r"(a[1]), "r"(a[2]), "r"(a[3]),
          "r"(b0), "r"(b1));
}

__device__ __forceinline__ void ldsm4(uint32_t r[4], uint32_t addr) {
    asm volatile("ldmatrix.sync.aligned.m8n8.x4.shared.b16 {%0,%1,%2,%3}, [%4];"
                 : "=r"(r[0]), "=r"(r[1]), "=r"(r[2]), "=r"(r[3]) : "r"(addr));
}
__device__ __forceinline__ void cpasync16(uint32_t saddr, const void* g) {
    asm volatile("cp.async.cg.shared.global [%0], [%1], 16;" :: "r"(saddr), "l"(g));
}
#define CP_COMMIT() asm volatile("cp.async.commit_group;" ::: "memory")
#define CP_WAIT0()  asm volatile("cp.async.wait_group 0;" ::: "memory")

// ---------------------------------------------------------------------------
// Elementwise split: fp32 -> hi/lo bf16 planes (pairs packed in u32).
// ---------------------------------------------------------------------------
__global__ void __launch_bounds__(256) split_pairs(
    const float* __restrict__ src,
    uint32_t* __restrict__ dhi, uint32_t* __restrict__ dlo, size_t npairs)
{
    size_t i = (size_t)blockIdx.x * 256 + threadIdx.x;
    if (i >= npairs) return;
    float x0 = src[2 * i], x1 = src[2 * i + 1];
    uint32_t hw, lw;
    split_pair_words(x0, x1, hw, lw);
    dhi[i] = hw;
    dlo[i] = lw;
}

// ---------------------------------------------------------------------------
// Tiled transpose + split: src fp32 [R][C] -> dst hi/lo bf16 [C][R].
// ---------------------------------------------------------------------------
__global__ void __launch_bounds__(256) transpose_split(
    const float* __restrict__ src,
    uint32_t* __restrict__ dhi, uint32_t* __restrict__ dlo,
    int R, int C)
{
    __shared__ float s[64][33];
    const int b = blockIdx.z;
    src += (size_t)b * R * C;
    const size_t dbatch = (size_t)C * (R >> 1);
    dhi += (size_t)b * dbatch;
    dlo += (size_t)b * dbatch;

    const int c0 = blockIdx.x * 32;
    const int r0 = blockIdx.y * 64;
    const int tx = threadIdx.x, ty = threadIdx.y;

    #pragma unroll
    for (int j = 0; j < 8; j++) {
        const int r = ty + 8 * j;
        s[r][tx] = src[(size_t)(r0 + r) * C + c0 + tx];
    }
    __syncthreads();

    #pragma unroll
    for (int j = 0; j < 4; j++) {
        const int cl = ty + 8 * j;
        const float x0 = s[2 * tx][cl];
        const float x1 = s[2 * tx + 1][cl];
        uint32_t hw, lw;
        split_pair_words(x0, x1, hw, lw);
        const size_t o = (size_t)(c0 + cl) * (R >> 1) + (r0 >> 1) + tx;
        dhi[o] = hw;
        dlo[o] = lw;
    }
}

// ---------------------------------------------------------------------------
// Split-bf16 tensor-core GEMM, cp.async double buffer + ldmatrix fragments.
//   C[m][n] = sum_k A[m][k] * B[n][k]  (both operands R-layout hi/lo planes)
// 128x128 CTA tile, 256 threads, 8 warps = 2(m) x 4(n), warp tile 64x32,
// m16n8k16 atoms, 3 MMAs per atom (ah*bh + ah*bl + al*bh), fp32 accumulate.
// Round-5 liveness profile (one bv[4] live at a time); within each nt block
// MMAs are issued term-major so accumulator reuse distance is 4, not 1.
// ---------------------------------------------------------------------------
template<bool BIAS, bool OSPLIT>
__global__ void __launch_bounds__(256, 2) bgemm(
    const uint32_t* __restrict__ Ahi32, const uint32_t* __restrict__ Alo32,
    int lda, size_t sA,
    const uint32_t* __restrict__ Bhi32, const uint32_t* __restrict__ Blo32,
    int ldb, size_t sB,
    const float* __restrict__ bias,
    float* __restrict__ C, uint32_t* __restrict__ Chi, uint32_t* __restrict__ Clo,
    int ldc, size_t sC, int Ktot)
{
    __shared__ uint32_t As[2][128 * PS];
    __shared__ uint32_t Bs[2][128 * PS];

    const int bz = blockIdx.z;
    const __nv_bfloat16* Ahi = (const __nv_bfloat16*)Ahi32 + sA * bz;
    const __nv_bfloat16* Alo = (const __nv_bfloat16*)Alo32 + sA * bz;
    const __nv_bfloat16* Bhi = (const __nv_bfloat16*)Bhi32 + sB * bz;
    const __nv_bfloat16* Blo = (const __nv_bfloat16*)Blo32 + sB * bz;

    const int tid = threadIdx.x;
    const int m0  = blockIdx.x * 128;
    const int n0  = blockIdx.y * 128;

    // cp.async loader: thread -> (row, plane); copies 2x16B per operand/stage
    const int lrow = tid >> 1;
    const int lpl  = tid & 1;
    const __nv_bfloat16* Asrc = (lpl ? Alo : Ahi) + (size_t)(m0 + lrow) * lda;
    const __nv_bfloat16* Bsrc = (lpl ? Blo : Bhi) + (size_t)(n0 + lrow) * ldb;
    const uint32_t sdst = (uint32_t)(lrow * PS + lpl * 8) * 4;   // bytes in stage

    const uint32_t aS = (uint32_t)__cvta_generic_to_shared(&As[0][0]);
    const uint32_t bS = (uint32_t)__cvta_generic_to_shared(&Bs[0][0]);
    const uint32_t stageB = 128 * PS * 4;

    // warp/lane decomposition
    const int wid = tid >> 5, lane = tid & 31;
    const int wm = (wid & 1) * 64;
    const int wn = (wid >> 1) * 32;
    const int qr = lane >> 2, qc = lane & 3;

    // ldmatrix per-lane addresses (byte offsets within a stage)
    uint32_t aoff[4], boff[4];
    {
        const int arl = (lane & 7) + (lane & 8);
        const int awd = (lane & 16) ? 4 : 0;
        #pragma unroll
        for (int mt = 0; mt < 4; mt++)
            aoff[mt] = (uint32_t)(((wm + mt * 16 + arl) * PS + awd) * 4);
        const int brl = lane & 7;
        const int bwd = ((lane >> 3) & 3) * 4;
        #pragma unroll
        for (int nt = 0; nt < 4; nt++)
            boff[nt] = (uint32_t)(((wn + nt * 8 + brl) * PS + bwd) * 4);
    }

    float acc[4][4][4];
    #pragma unroll
    for (int mt = 0; mt < 4; mt++)
        #pragma unroll
        for (int nt = 0; nt < 4; nt++)
            #pragma unroll
            for (int r = 0; r < 4; r++) acc[mt][nt][r] = 0.f;

    // ---- prologue: stage 0 ----
    cpasync16(aS + sdst,      Asrc);
    cpasync16(aS + sdst + 16, Asrc + 8);
    cpasync16(bS + sdst,      Bsrc);
    cpasync16(bS + sdst + 16, Bsrc + 8);
    CP_COMMIT();
    CP_WAIT0();
    __syncthreads();

    const int nk = Ktot / KC;
    int buf = 0;
    for (int kb = 0; kb < nk; kb++) {
        const bool has_next = (kb + 1) < nk;
        if (has_next) {
            const int k0 = (kb + 1) * KC;
            const uint32_t ad = aS + (buf ^ 1) * stageB + sdst;
            const uint32_t bd = bS + (buf ^ 1) * stageB + sdst;
            cpasync16(ad,      Asrc + k0);
            cpasync16(ad + 16, Asrc + k0 + 8);
            cpasync16(bd,      Bsrc + k0);
            cpasync16(bd + 16, Bsrc + k0 + 8);
            CP_COMMIT();
        }

        const uint32_t ab = aS + buf * stageB;
        const uint32_t bb = bS + buf * stageB;

        uint32_t ah[4][4], al[4][4];
        #pragma unroll
        for (int mt = 0; mt < 4; mt++) {
            ldsm4(ah[mt], ab + aoff[mt]);          // hi plane (words 0..7)
            ldsm4(al[mt], ab + aoff[mt] + 32);     // lo plane (words 8..15)
        }
        #pragma unroll
        for (int nt = 0; nt < 4; nt++) {
            uint32_t bv[4];                        // {b0h, b1h, b0l, b1l}
            ldsm4(bv, bb + boff[nt]);
            // term-major: each acc[mt][nt] reused at distance 4, not 1
            #pragma unroll
            for (int mt = 0; mt < 4; mt++)
                mma_bf16(acc[mt][nt], ah[mt], bv[2], bv[3]);   // ah*bl
            #pragma unroll
            for (int mt = 0; mt < 4; mt++)
                mma_bf16(acc[mt][nt], al[mt], bv[0], bv[1]);   // al*bh
            #pragma unroll
            for (int mt = 0; mt < 4; mt++)
                mma_bf16(acc[mt][nt], ah[mt], bv[0], bv[1]);   // ah*bh
        }

        if (has_next) {
            CP_WAIT0();
            __syncthreads();
            buf ^= 1;
        }
    }

    // ---- epilogue ----
    #pragma unroll
    for (int mt = 0; mt < 4; mt++) {
        #pragma unroll
        for (int nt = 0; nt < 4; nt++) {
            const int row = m0 + wm + mt * 16 + qr;
            const int col = n0 + wn + nt * 8 + 2 * qc;
            float v0 = acc[mt][nt][0], v1 = acc[mt][nt][1];
            float v2 = acc[mt][nt][2], v3 = acc[mt][nt][3];
            if (BIAS) {
                const float b0 = bias[col], b1 = bias[col + 1];
                v0 += b0; v1 += b1; v2 += b0; v3 += b1;
            }
            if (OSPLIT) {
                uint32_t* chb = Chi + (size_t)bz * (sC >> 1);
                uint32_t* clb = Clo + (size_t)bz * (sC >> 1);
                uint32_t hw, lw;
                split_pair_words(v0, v1, hw, lw);
                size_t o = (size_t)row * (ldc >> 1) + (col >> 1);
                chb[o] = hw; clb[o] = lw;
                split_pair_words(v2, v3, hw, lw);
                o = (size_t)(row + 8) * (ldc >> 1) + (col >> 1);
                chb[o] = hw; clb[o] = lw;
            } else {
                float* cb = C + sC * bz;
                *(float2*)&cb[(size_t)row * ldc + col]       = make_float2(v0, v1);
                *(float2*)&cb[(size_t)(row + 8) * ldc + col] = make_float2(v2, v3);
            }
        }
    }
}

// ---------------------------------------------------------------------------
// Fused row softmax + bf16 split: S[b][i][p] fp32 -> prob planes [b][i][p].
// One CTA per row (2304 elements cached in smem), 256 threads.
// ---------------------------------------------------------------------------
__global__ void __launch_bounds__(256) softmax_split(
    const float* __restrict__ S,
    uint32_t* __restrict__ ph_out, uint32_t* __restrict__ pl_out)
{
    __shared__ float row[NP];
    __shared__ float red[9];
    const int b = blockIdx.y, i = blockIdx.x, t = threadIdx.x;
    const int wid = t >> 5, lane = t & 31;
    const float* src = S + ((size_t)b * NP + i) * NP;

    float lm = -3.402823466e38f;
    #pragma unroll
    for (int j = 0; j < 9; j++) {
        const int idx = j * 256 + t;
        const float x = src[idx];
        row[idx] = x;
        lm = fmaxf(lm, x);
    }
    #pragma unroll
    for (int o = 16; o; o >>= 1) lm = fmaxf(lm, __shfl_xor_sync(0xffffffffu, lm, o));
    if (lane == 0) red[wid] = lm;
    __syncthreads();
    if (t == 0) {
        float M = red[0];
        #pragma unroll
        for (int k = 1; k < 8; k++) M = fmaxf(M, red[k]);
        red[8] = M;
    }
    __syncthreads();
    const float M = red[8];

    float ls = 0.f;
    #pragma unroll
    for (int j = 0; j < 9; j++) {
        const int idx = j * 256 + t;
        const float e = __expf(row[idx] - M);
        row[idx] = e;
        ls += e;
    }
    #pragma unroll
    for (int o = 16; o; o >>= 1) ls += __shfl_xor_sync(0xffffffffu, ls, o);
    if (lane == 0) red[wid] = ls;
    __syncthreads();
    if (t == 0) {
        float s2 = 0.f;
        #pragma unroll
        for (int k = 0; k < 8; k++) s2 += red[k];
        red[8] = 1.0f / s2;
    }
    __syncthreads();
    const float inv = red[8];

    uint32_t* oh = ph_out + ((size_t)b * NP + i) * (NP / 2);
    uint32_t* ol = pl_out + ((size_t)b * NP + i) * (NP / 2);
    #pragma unroll
    for (int j = 0; j < 5; j++) {
        const int q = j * 256 + t;
        if (q < NP / 2) {
            const float2 xv = *(const float2*)&row[2 * q];
            uint32_t hw, lw;
            split_pair_words(xv.x * inv, xv.y * inv, hw, lw);
            oh[q] = hw;
            ol[q] = lw;
        }
    }
}

// ---------------------------------------------------------------------------
extern "C" void kernel_launch(void* const* d_in, const int* in_sizes, int n_in,
                              void* d_out, int out_size)
{
    const float* qf = (const float*)d_in[0];   // [B, CQ, 48, 48]
    const float* rf = (const float*)d_in[1];   // [B, CR, 48, 48]
    const float* Wq = (const float*)d_in[2];   // [HID, CQ]
    const float* bq = (const float*)d_in[3];   // [HID]
    const float* Wk = (const float*)d_in[4];   // [HID, CR]
    const float* bk = (const float*)d_in[5];   // [HID]
    float* out = (float*)d_out;                // [B, CR, 48, 48]

    uint32_t *qfTh, *qfTl, *rfTh, *rfTl, *rfSh, *rfSl;
    uint32_t *Wqh, *Wql, *Wkh, *Wkl, *Qh, *Ql, *Kh, *Kl, *ath, *atl;
    float *Ap;
    cudaGetSymbolAddress((void**)&qfTh, g_qfT_hi);
    cudaGetSymbolAddress((void**)&qfTl, g_qfT_lo);
    cudaGetSymbolAddress((void**)&rfTh, g_rfT_hi);
    cudaGetSymbolAddress((void**)&rfTl, g_rfT_lo);
    cudaGetSymbolAddress((void**)&rfSh, g_rfS_hi);
    cudaGetSymbolAddress((void**)&rfSl, g_rfS_lo);
    cudaGetSymbolAddress((void**)&Wqh, g_Wq_hi);
    cudaGetSymbolAddress((void**)&Wql, g_Wq_lo);
    cudaGetSymbolAddress((void**)&Wkh, g_Wk_hi);
    cudaGetSymbolAddress((void**)&Wkl, g_Wk_lo);
    cudaGetSymbolAddress((void**)&Qh, g_Q_hi);
    cudaGetSymbolAddress((void**)&Ql, g_Q_lo);
    cudaGetSymbolAddress((void**)&Kh, g_K_hi);
    cudaGetSymbolAddress((void**)&Kl, g_K_lo);
    cudaGetSymbolAddress((void**)&ath, g_at_hi);
    cudaGetSymbolAddress((void**)&atl, g_at_lo);
    cudaGetSymbolAddress((void**)&Ap, g_attn);

    // ---- prepass: splits + transposes ----
    {
        size_t np;
        np = (size_t)HID * CQ / 2;
        split_pairs<<<(unsigned)((np + 255) / 256), 256>>>(Wq, Wqh, Wql, np);
        np = (size_t)HID * CR / 2;
        split_pairs<<<(unsigned)((np + 255) / 256), 256>>>(Wk, Wkh, Wkl, np);
        np = (size_t)BB * CR * NP / 2;
        split_pairs<<<(unsigned)((np + 255) / 256), 256>>>(rf, rfSh, rfSl, np);
    }
    transpose_split<<<dim3(NP / 32, CQ / 64, BB), dim3(32, 8)>>>(qf, qfTh, qfTl, CQ, NP);
    transpose_split<<<dim3(NP / 32, CR / 64, BB), dim3(32, 8)>>>(rf, rfTh, rfTl, CR, NP);

    // ---- GEMM1: Q[i][o] = qfT[i][c] * Wq[o][c] + bq -> hi/lo planes ----
    bgemm<true, true><<<dim3(NP / 128, HID / 128, BB), 256>>>(
        qfTh, qfTl, CQ, (size_t)NP * CQ,
        Wqh, Wql, CQ, 0,
        bq,
        nullptr, Qh, Ql, HID, (size_t)NP * HID,
        CQ);

    // ---- GEMM2: K[p][o] = rfT[p][c] * Wk[o][c] + bk -> hi/lo planes ----
    bgemm<true, true><<<dim3(NP / 128, HID / 128, BB), 256>>>(
        rfTh, rfTl, CR, (size_t)NP * CR,
        Wkh, Wkl, CR, 0,
        bk,
        nullptr, Kh, Kl, HID, (size_t)NP * HID,
        CR);

    // ---- GEMM3: S[i][p] = Q[i][k] * K[p][k]  (fp32 out) ----
    bgemm<false, false><<<dim3(NP / 128, NP / 128, BB), 256>>>(
        Qh, Ql, HID, (size_t)NP * HID,
        Kh, Kl, HID, (size_t)NP * HID,
        nullptr,
        Ap, nullptr, nullptr, NP, (size_t)NP * NP,
        HID);

    // ---- fused softmax over p + bf16 split to prob planes [i][p] ----
    softmax_split<<<dim3(NP, BB), 256>>>(Ap, ath, atl);

    // ---- GEMM4: out[c][i] = rfS[c][p] * attn[i][p]  (fp32 out) ----
    bgemm<false, false><<<dim3(CR / 128, NP / 128, BB), 256>>>(
        rfSh, rfSl, NP, (size_t)CR * NP,
        ath, atl, NP, (size_t)NP * NP,
        nullptr,
        out, nullptr, nullptr, NP, (size_t)CR * NP,
        NP);
}